// round 14
// baseline (speedup 1.0000x reference)
#include <cuda_runtime.h>
#include <cuda_fp16.h>
#include <math.h>
#include <cstdint>

#define BATCH 2
#define SEQ   2048
#define NTOK  (BATCH*SEQ)      // 4096
#define DIM   1024
#define HEADS 16
#define HDIM  64
#define WIN   128
#define SCALE 0.125f           // 1/sqrt(64)

// Scratch (device globals; no allocation allowed)
__device__ __half g_qin[NTOK*DIM];    // rope output, fp16
__device__ __half g_xr [NTOK*DIM];    // x, fp16
__device__ __half g_q  [NTOK*DIM];    // Q fp16
__device__ __half g_k  [NTOK*DIM];    // K fp16
__device__ __half g_vt [NTOK*DIM];    // V^T fp16: [(b*16+h)*64+d][s]
__device__ __half g_ao [NTOK*DIM];    // attention out fp16
__device__ __half g_wr [4*DIM*DIM];   // W^T fp16: [mat][n][k]
__device__ unsigned int g_tctr;       // persistent-GEMM tile counter

#define CPA(dst, src) \
    asm volatile("cp.async.cg.shared.global [%0], [%1], 16;" :: "r"(dst), "l"(src) : "memory")
#define CPC() asm volatile("cp.async.commit_group;" ::: "memory")
#define CPW(n) asm volatile("cp.async.wait_group %0;" :: "n"(n) : "memory")
#define LDM4(r0, r1, r2, r3, a) \
    asm volatile("ldmatrix.sync.aligned.m8n8.x4.shared.b16 {%0,%1,%2,%3}, [%4];" \
        : "=r"(r0), "=r"(r1), "=r"(r2), "=r"(r3) : "r"(a))

__device__ __forceinline__ uint32_t smem_u32(const void* p) {
    uint32_t a;
    asm("{ .reg .u64 t; cvta.to.shared.u64 t, %1; cvt.u32.u64 %0, t; }" : "=r"(a) : "l"(p));
    return a;
}

__device__ __forceinline__ void mma_f16(float* c, const uint32_t* a, const uint32_t* b) {
    asm volatile(
        "mma.sync.aligned.m16n8k16.row.col.f32.f16.f16.f32 "
        "{%0,%1,%2,%3}, {%4,%5,%6,%7}, {%8,%9}, {%0,%1,%2,%3};"
        : "+f"(c[0]), "+f"(c[1]), "+f"(c[2]), "+f"(c[3])
        : "r"(a[0]), "r"(a[1]), "r"(a[2]), "r"(a[3]), "r"(b[0]), "r"(b[1]));
}

// ===========================================================================
// Weight prep: transpose + fp16-round.  zsel picks which matrices.
// ===========================================================================
__global__ void prep_w3(const float* __restrict__ w0, const float* __restrict__ w1,
                        const float* __restrict__ w2) {
    __shared__ float t[32][33];
    const int z = blockIdx.z;
    const float* w = (z == 0) ? w0 : (z == 1) ? w1 : w2;
    const int k0 = blockIdx.y * 32, n0 = blockIdx.x * 32;
    for (int r = threadIdx.y; r < 32; r += 8)
        t[r][threadIdx.x] = w[(size_t)(k0 + r) * DIM + n0 + threadIdx.x];
    __syncthreads();
    __half* o = g_wr + (size_t)z * DIM * DIM;
    for (int r = threadIdx.y; r < 32; r += 8)
        o[(size_t)(n0 + r) * DIM + k0 + threadIdx.x] = __float2half_rn(t[threadIdx.x][r]);
}

__global__ void prep_wo(const float* __restrict__ w3) {
    __shared__ float t[32][33];
    const int k0 = blockIdx.y * 32, n0 = blockIdx.x * 32;
    for (int r = threadIdx.y; r < 32; r += 8)
        t[r][threadIdx.x] = w3[(size_t)(k0 + r) * DIM + n0 + threadIdx.x];
    __syncthreads();
    __half* o = g_wr + (size_t)3 * DIM * DIM;
    for (int r = threadIdx.y; r < 32; r += 8)
        o[(size_t)(n0 + r) * DIM + k0 + threadIdx.x] = __float2half_rn(t[threadIdx.x][r]);
}

// ===========================================================================
// RoPE + x rounding; resets the persistent tile counter.
// ===========================================================================
__global__ void rope_kernel(const float* __restrict__ x) {
    int idx = blockIdx.x * blockDim.x + threadIdx.x;   // NTOK*512
    if (idx == 0) g_tctr = 0;
    if (idx >= NTOK * 512) return;
    int t   = idx >> 9;
    int rem = idx & 511;
    int h   = rem >> 5;
    int i   = rem & 31;
    int s   = t & (SEQ - 1);

    float inv = expf(-(float)i * (9.210340371976184f / 32.0f));
    float ang = (float)s * inv;
    float sn, cs;
    sincosf(ang, &sn, &cs);

    const float* xp = x     + (size_t)t * DIM + h * HDIM;
    __half*      qp = g_qin + (size_t)t * DIM + h * HDIM;
    __half*      xr = g_xr  + (size_t)t * DIM + h * HDIM;
    float x1 = xp[i];
    float x2 = xp[i + 32];
    qp[i]      = __float2half_rn(x1 * cs - x2 * sn);
    qp[i + 32] = __float2half_rn(x2 * cs + x1 * sn);
    xr[i]      = __float2half_rn(x1);
    xr[i + 32] = __float2half_rn(x2);
}

// ===========================================================================
// FP16 GEMM (unchanged): CTA 128x128, 256 thr, warp tile 32x64, BK=64,
// 3-stage cp.async, ldmatrix; 110.6KB smem -> 2 CTAs/SM.
// ===========================================================================
#define RSTRH 72
#define A_BYTES (128 * RSTRH * 2)      // 18432
#define B_BYTES (128 * RSTRH * 2)      // 18432
#define SSZ     (A_BYTES + B_BYTES)    // 36864
#define GEMM_SMEM_BYTES (3 * SSZ)      // 110592
#define NCHUNK  (DIM / 64)             // 16

extern __shared__ uint32_t dsm[];

template <int MODE, typename OutT>
__device__ __forceinline__ void gemm_body(const __half* __restrict__ A,
                                          const __half* __restrict__ Wt,
                                          OutT* __restrict__ C,
                                          int row0, int col0) {
    const int tid  = threadIdx.x;
    const int wid  = tid >> 5;
    const int lane = tid & 31;
    const int gid  = lane >> 2;
    const int tig  = lane & 3;
    const int wm   = wid >> 1;
    const int wn   = wid & 1;
    const int mi   = lane >> 3;
    const int lr   = lane & 7;

    const uint32_t sb = smem_u32(dsm);

    const uint32_t a_lane = ((wm * 32 + (mi & 1) * 8 + lr) * RSTRH + (mi >> 1) * 8) * 2;
    const uint32_t b_lane = ((wn * 64 + (mi >> 1) * 8 + lr) * RSTRH + (mi & 1) * 8) * 2;

    float acc[2][8][4];
#pragma unroll
    for (int i = 0; i < 2; i++)
#pragma unroll
        for (int j = 0; j < 8; j++)
#pragma unroll
            for (int r = 0; r < 4; r++) acc[i][j][r] = 0.0f;

#define ISSUE_STAGE(s, c)                                                        \
    {                                                                            \
        uint32_t ab = sb + (s) * SSZ;                                            \
        uint32_t bb = ab + A_BYTES;                                              \
        _Pragma("unroll")                                                        \
        for (int it = 0; it < 4; it++) {                                         \
            int idx = it * 256 + tid;                                            \
            int m = idx >> 3, k8 = idx & 7;                                      \
            CPA(ab + m * 144 + k8 * 16,                                          \
                A + (size_t)(row0 + m) * DIM + (c) * 64 + k8 * 8);               \
            CPA(bb + m * 144 + k8 * 16,                                          \
                Wt + (size_t)(col0 + m) * DIM + (c) * 64 + k8 * 8);              \
        }                                                                        \
        CPC();                                                                   \
    }

    ISSUE_STAGE(0, 0);
    ISSUE_STAGE(1, 1);

    int s = 0;
    for (int c = 0; c < NCHUNK; c++) {
        CPW(1);
        __syncthreads();
        if (c + 2 < NCHUNK) {
            int sn = (s + 2 >= 3) ? s - 1 : s + 2;
            ISSUE_STAGE(sn, c + 2);
        }

        const uint32_t abase = sb + s * SSZ;
        const uint32_t bbase = abase + A_BYTES;
#pragma unroll
        for (int ss = 0; ss < 4; ss++) {
            const int ksf = ss * 32;
            uint32_t af[2][4], bf[8][2];
#pragma unroll
            for (int i = 0; i < 2; i++)
                LDM4(af[i][0], af[i][1], af[i][2], af[i][3],
                     abase + a_lane + i * (16 * RSTRH * 2) + ksf);
#pragma unroll
            for (int jj = 0; jj < 4; jj++)
                LDM4(bf[2 * jj][0], bf[2 * jj][1], bf[2 * jj + 1][0], bf[2 * jj + 1][1],
                     bbase + b_lane + jj * (16 * RSTRH * 2) + ksf);
#pragma unroll
            for (int i = 0; i < 2; i++)
#pragma unroll
                for (int j = 0; j < 8; j++)
                    mma_f16(acc[i][j], af[i], bf[j]);
        }
        s = (s + 1 == 3) ? 0 : s + 1;
    }

#pragma unroll
    for (int i = 0; i < 2; i++) {
        int r0 = row0 + wm * 32 + i * 16 + gid;
#pragma unroll
        for (int j = 0; j < 8; j++) {
            int cc = col0 + wn * 64 + j * 8 + tig * 2;
            if (MODE == 0) {
                float* Cf = (float*)C;
                *(float2*)(Cf + (size_t)r0 * DIM + cc)       = make_float2(acc[i][j][0], acc[i][j][1]);
                *(float2*)(Cf + (size_t)(r0 + 8) * DIM + cc) = make_float2(acc[i][j][2], acc[i][j][3]);
            } else if (MODE == 1) {
                __half* Ch = (__half*)C;
                *(__half2*)(Ch + (size_t)r0 * DIM + cc) =
                    __floats2half2_rn(acc[i][j][0], acc[i][j][1]);
                *(__half2*)(Ch + (size_t)(r0 + 8) * DIM + cc) =
                    __floats2half2_rn(acc[i][j][2], acc[i][j][3]);
            } else {
                __half* Ch = (__half*)C;
                int b0 = r0 >> 11, s0 = r0 & 2047;
                int hh = cc >> 6,  dd = cc & 63;
                __half* base = Ch + ((size_t)(b0 * HEADS + hh) * HDIM) * SEQ;
                base[(size_t)(dd)     * SEQ + s0] = __float2half_rn(acc[i][j][0]);
                base[(size_t)(dd + 1) * SEQ + s0] = __float2half_rn(acc[i][j][1]);
                int r1 = r0 + 8;
                int b1 = r1 >> 11, s1 = r1 & 2047;
                __half* base1 = Ch + ((size_t)(b1 * HEADS + hh) * HDIM) * SEQ;
                base1[(size_t)(dd)     * SEQ + s1] = __float2half_rn(acc[i][j][2]);
                base1[(size_t)(dd + 1) * SEQ + s1] = __float2half_rn(acc[i][j][3]);
            }
        }
    }
}

#define QKV_TILES 768

__global__ __launch_bounds__(256, 2)
void gemm_qkv() {
    __shared__ unsigned int s_tile;
    for (;;) {
        __syncthreads();
        if (threadIdx.x == 0) s_tile = atomicAdd(&g_tctr, 1u);
        __syncthreads();
        unsigned int tile = s_tile;
        if (tile >= QKV_TILES) return;

        const int mi   = tile >> 8;
        const int rem  = tile & 255;
        const int row0 = (rem >> 3) * 128;
        const int col0 = (rem & 7) * 128;
        const __half* Wt = g_wr + (size_t)mi * DIM * DIM;
        if (mi == 0)      gemm_body<1>(g_qin, Wt, g_q,  row0, col0);
        else if (mi == 1) gemm_body<1>(g_qin, Wt, g_k,  row0, col0);
        else              gemm_body<2>(g_xr,  Wt, g_vt, row0, col0);
    }
}

__global__ __launch_bounds__(256, 2)
void gemm_out(float* __restrict__ out) {
    gemm_body<0>(g_ao, g_wr + (size_t)3 * DIM * DIM, out, blockIdx.y * 128, blockIdx.x * 128);
}

// ===========================================================================
// FP16 MMA attention v3 (unchanged): double-buffered K/V, mask special-
// ization, two j-halves, 3 CTAs/SM.
// ===========================================================================
#define KVSZ (64 * RSTRH * 2)          // 9216 B
#define ATTN_SMEM_BYTES (128*RSTRH*2 + 4*KVSZ + 128*RSTRH*2)  // 73728

__global__ __launch_bounds__(256, 3)
void attn_mma() {
    extern __shared__ __half afh[];

    const int tid  = threadIdx.x;
    const int wid  = tid >> 5;
    const int lane = tid & 31;
    const int gid  = lane >> 2;
    const int tig  = lane & 3;
    const int mi   = lane >> 3;
    const int lr   = lane & 7;

    const int qt = blockIdx.x, h = blockIdx.y, b = blockIdx.z;
    const int q0 = qt * 128;

    const uint32_t sb = smem_u32(afh);
    const uint32_t Qb = sb;
    const uint32_t KV0 = sb + 128 * RSTRH * 2;
    const uint32_t Pb  = KV0 + 4 * KVSZ;
    __half* Ps_h = afh + 128 * RSTRH + 4 * 64 * RSTRH;

    const __half* Qg = g_q + ((size_t)(b * SEQ + q0)) * DIM + h * HDIM;
#pragma unroll
    for (int it = 0; it < 4; it++) {
        int idx = it * 256 + tid;
        int r = idx >> 3, c8 = idx & 7;
        CPA(Qb + r * 144 + c8 * 16, Qg + (size_t)r * DIM + c8 * 8);
    }
    CPC();

    const __half* Kgb = g_k  + ((size_t)(b * SEQ)) * DIM + h * HDIM;
    const __half* Vgb = g_vt + ((size_t)((b * HEADS + h) * HDIM)) * SEQ;

#define ISSUE_KV(kt0, nb)                                                        \
    {                                                                            \
        uint32_t kb = KV0 + (nb) * 2 * KVSZ;                                     \
        uint32_t vb = kb + KVSZ;                                                 \
        const __half* Kg = Kgb + (size_t)(kt0) * DIM;                            \
        const __half* Vg = Vgb + (kt0);                                          \
        _Pragma("unroll")                                                        \
        for (int it = 0; it < 2; it++) {                                         \
            int idx = it * 256 + tid;                                            \
            int r = idx >> 3, c8 = idx & 7;                                      \
            CPA(kb + r * 144 + c8 * 16, Kg + (size_t)r * DIM + c8 * 8);          \
            CPA(vb + r * 144 + c8 * 16, Vg + (size_t)r * SEQ + c8 * 8);          \
        }                                                                        \
        CPC();                                                                   \
    }

    const uint32_t a_q = Qb + ((16 * wid + (mi & 1) * 8 + lr) * RSTRH + (mi >> 1) * 8) * 2;
    const uint32_t a_p = Pb + ((16 * wid + (mi & 1) * 8 + lr) * RSTRH + (mi >> 1) * 8) * 2;
    const uint32_t boff = ((mi >> 1) * 8 + lr) * 144 + (mi & 1) * 16;

    float o[8][4];
#pragma unroll
    for (int j = 0; j < 8; j++)
#pragma unroll
        for (int r = 0; r < 4; r++) o[j][r] = 0.0f;
    float lp0 = 0.0f, lp1 = 0.0f;
    const int r0g = q0 + 16 * wid + gid;

    const int p_lo = (q0 == 0) ? 2 : 0;
    const int p_hi = min(5, (SEQ + 64 - q0) / 64);

    ISSUE_KV(q0 - 128 + p_lo * 64, 0);

    int nb = 0;
    for (int p = p_lo; p <= p_hi; p++) {
        const int kt0 = q0 - 128 + p * 64;

        __syncthreads();
        if (p < p_hi) { ISSUE_KV(kt0 + 64, nb ^ 1); CPW(1); }
        else CPW(0);
        __syncthreads();

        const int d = q0 + 16 * wid - kt0;     // warp-uniform
        if (d > -143 && d < 191) {
            const uint32_t kbuf = KV0 + nb * 2 * KVSZ;
            const uint32_t vbuf = kbuf + KVSZ;
            const bool full = (d >= -64) && (d <= 112);

#pragma unroll
            for (int jh = 0; jh < 2; jh++) {
                float sc[4][4];
#pragma unroll
                for (int j = 0; j < 4; j++)
#pragma unroll
                    for (int r = 0; r < 4; r++) sc[j][r] = 0.0f;
#pragma unroll
                for (int ss = 0; ss < 4; ss++) {
                    uint32_t aq[4], bf[4][2];
                    LDM4(aq[0], aq[1], aq[2], aq[3], a_q + ss * 32);
#pragma unroll
                    for (int jj = 0; jj < 2; jj++)
                        LDM4(bf[2*jj][0], bf[2*jj][1], bf[2*jj+1][0], bf[2*jj+1][1],
                             kbuf + (jh * 2 + jj) * (16 * RSTRH * 2) + boff + ss * 32);
#pragma unroll
                    for (int j = 0; j < 4; j++) mma_f16(sc[j], aq, bf[j]);
                }

#pragma unroll
                for (int j = 0; j < 4; j++) {
                    const int jg = jh * 4 + j;
                    __half2 h01, h23;
                    if (full) {
                        float e0 = __expf(sc[j][0] * SCALE);
                        float e1 = __expf(sc[j][1] * SCALE);
                        float e2 = __expf(sc[j][2] * SCALE);
                        float e3 = __expf(sc[j][3] * SCALE);
                        lp0 += e0 + e1;
                        lp1 += e2 + e3;
                        h01 = __floats2half2_rn(e0, e1);
                        h23 = __floats2half2_rn(e2, e3);
                    } else {
                        const int dj = d - 8 * jg;
                        if (dj >= 135 || dj <= -143) {
                            h01 = __half2(__float2half_rn(0.f), __float2half_rn(0.f));
                            h23 = h01;
                        } else {
                            int col = kt0 + jg * 8 + 2 * tig;
                            float e0 = (abs(r0g - col)     < WIN) ? __expf(sc[j][0] * SCALE) : 0.0f;
                            float e1 = (abs(r0g - col - 1) < WIN) ? __expf(sc[j][1] * SCALE) : 0.0f;
                            float e2 = (abs(r0g + 8 - col)     < WIN) ? __expf(sc[j][2] * SCALE) : 0.0f;
                            float e3 = (abs(r0g + 8 - col - 1) < WIN) ? __expf(sc[j][3] * SCALE) : 0.0f;
                            lp0 += e0 + e1;
                            lp1 += e2 + e3;
                            h01 = __floats2half2_rn(e0, e1);
                            h23 = __floats2half2_rn(e2, e3);
                        }
                    }
                    *(__half2*)&Ps_h[(16 * wid + gid) * RSTRH + jg * 8 + 2 * tig]     = h01;
                    *(__half2*)&Ps_h[(16 * wid + gid + 8) * RSTRH + jg * 8 + 2 * tig] = h23;
                }
            }
            __syncwarp();

#pragma unroll
            for (int ss = 0; ss < 4; ss++) {
                uint32_t ap[4], bf[8][2];
                LDM4(ap[0], ap[1], ap[2], ap[3], a_p + ss * 32);
#pragma unroll
                for (int jj = 0; jj < 4; jj++)
                    LDM4(bf[2*jj][0], bf[2*jj][1], bf[2*jj+1][0], bf[2*jj+1][1],
                         vbuf + jj * (16 * RSTRH * 2) + boff + ss * 32);
#pragma unroll
                for (int j = 0; j < 8; j++) mma_f16(o[j], ap, bf[j]);
            }
        }
        nb ^= 1;
    }

    lp0 += __shfl_xor_sync(0xffffffff, lp0, 1);
    lp0 += __shfl_xor_sync(0xffffffff, lp0, 2);
    lp1 += __shfl_xor_sync(0xffffffff, lp1, 1);
    lp1 += __shfl_xor_sync(0xffffffff, lp1, 2);
    const float inv0 = 1.0f / lp0;
    const float inv1 = 1.0f / lp1;

    __half* Og = g_ao + ((size_t)(b * SEQ + r0g)) * DIM + h * HDIM;
#pragma unroll
    for (int j = 0; j < 8; j++) {
        int c = j * 8 + 2 * tig;
        *(__half2*)(Og + c) = __floats2half2_rn(o[j][0] * inv0, o[j][1] * inv0);
        *(__half2*)(Og + (size_t)8 * DIM + c) = __floats2half2_rn(o[j][2] * inv1, o[j][3] * inv1);
    }
}

// ===========================================================================
extern "C" void kernel_launch(void* const* d_in, const int* in_sizes, int n_in,
                              void* d_out, int out_size) {
    const float* x  = (const float*)d_in[0];
    const float* Wq = (const float*)d_in[1];
    const float* Wk = (const float*)d_in[2];
    const float* Wv = (const float*)d_in[3];
    const float* Wo = (const float*)d_in[4];
    float* out = (float*)d_out;

    // One-time host-side setup (first call is the uncaptured correctness run;
    // replays reuse identical objects -> identical captured DAG every time).
    static cudaStream_t s1 = nullptr, s2 = nullptr;
    static cudaEvent_t ef1, ef2, ej1, ej2;
    static bool attr_done = false;
    if (!s1) {
        cudaStreamCreateWithFlags(&s1, cudaStreamNonBlocking);
        cudaStreamCreateWithFlags(&s2, cudaStreamNonBlocking);
        cudaEventCreateWithFlags(&ef1, cudaEventDisableTiming);
        cudaEventCreateWithFlags(&ef2, cudaEventDisableTiming);
        cudaEventCreateWithFlags(&ej1, cudaEventDisableTiming);
        cudaEventCreateWithFlags(&ej2, cudaEventDisableTiming);
    }
    if (!attr_done) {
        cudaFuncSetAttribute(gemm_qkv,
                             cudaFuncAttributeMaxDynamicSharedMemorySize, GEMM_SMEM_BYTES);
        cudaFuncSetAttribute(gemm_out,
                             cudaFuncAttributeMaxDynamicSharedMemorySize, GEMM_SMEM_BYTES);
        cudaFuncSetAttribute(attn_mma,
                             cudaFuncAttributeMaxDynamicSharedMemorySize, ATTN_SMEM_BYTES);
        attr_done = true;
    }

    // Fork side branches off the (captured) default stream.
    cudaEventRecord(ef1, 0);
    cudaStreamWaitEvent(s1, ef1, 0);
    cudaEventRecord(ef2, 0);
    cudaStreamWaitEvent(s2, ef2, 0);

    // s1: Wq/Wk/Wv transpose+round (overlaps rope)
    prep_w3<<<dim3(32, 32, 3), dim3(32, 8), 0, s1>>>(Wq, Wk, Wv);
    cudaEventRecord(ej1, s1);

    // s2: Wo transpose+round (overlaps rope + qkv + attention)
    prep_wo<<<dim3(32, 32), dim3(32, 8), 0, s2>>>(Wo);
    cudaEventRecord(ej2, s2);

    // s0: RoPE + x rounding (resets tile counter)
    rope_kernel<<<(NTOK * 512 + 255) / 256, 256>>>(x);

    // join s1, then Q,K,V projections — persistent, 296 CTAs (2/SM)
    cudaStreamWaitEvent(0, ej1, 0);
    gemm_qkv<<<296, 256, GEMM_SMEM_BYTES>>>();

    // FP16 MMA windowed attention (3 CTAs/SM)
    attn_mma<<<dim3(SEQ / 128, HEADS, BATCH), 256, ATTN_SMEM_BYTES>>>();

    // join s2, then output projection -> d_out (fp32)
    cudaStreamWaitEvent(0, ej2, 0);
    gemm_out<<<dim3(8, 32), 256, GEMM_SMEM_BYTES>>>(out);
    (void)in_sizes; (void)n_in; (void)out_size;
}

// round 15
// speedup vs baseline: 1.0099x; 1.0099x over previous
#include <cuda_runtime.h>
#include <cuda_fp16.h>
#include <math.h>
#include <cstdint>

#define BATCH 2
#define SEQ   2048
#define NTOK  (BATCH*SEQ)      // 4096
#define DIM   1024
#define HEADS 16
#define HDIM  64
#define WIN   128
#define SCALE 0.125f           // 1/sqrt(64)

// Scratch (device globals; no allocation allowed)
__device__ __half g_qin[NTOK*DIM];    // rope output, fp16
__device__ __half g_xr [NTOK*DIM];    // x, fp16
__device__ __half g_q  [NTOK*DIM];    // Q fp16
__device__ __half g_k  [NTOK*DIM];    // K fp16
__device__ __half g_vt [NTOK*DIM];    // V^T fp16: [(b*16+h)*64+d][s]
__device__ __half g_ao [NTOK*DIM];    // attention out fp16
__device__ __half g_wr [4*DIM*DIM];   // W^T fp16: [mat][n][k]
__device__ unsigned int g_tctr;       // persistent-GEMM tile counter

#define CPA(dst, src) \
    asm volatile("cp.async.cg.shared.global [%0], [%1], 16;" :: "r"(dst), "l"(src) : "memory")
#define CPC() asm volatile("cp.async.commit_group;" ::: "memory")
#define CPW(n) asm volatile("cp.async.wait_group %0;" :: "n"(n) : "memory")
#define LDM4(r0, r1, r2, r3, a) \
    asm volatile("ldmatrix.sync.aligned.m8n8.x4.shared.b16 {%0,%1,%2,%3}, [%4];" \
        : "=r"(r0), "=r"(r1), "=r"(r2), "=r"(r3) : "r"(a))

__device__ __forceinline__ uint32_t smem_u32(const void* p) {
    uint32_t a;
    asm("{ .reg .u64 t; cvta.to.shared.u64 t, %1; cvt.u32.u64 %0, t; }" : "=r"(a) : "l"(p));
    return a;
}

__device__ __forceinline__ uint32_t pack_h2(float a, float b) {
    __half2 t = __floats2half2_rn(a, b);
    return *(uint32_t*)&t;
}

__device__ __forceinline__ void mma_f16(float* c, const uint32_t* a, const uint32_t* b) {
    asm volatile(
        "mma.sync.aligned.m16n8k16.row.col.f32.f16.f16.f32 "
        "{%0,%1,%2,%3}, {%4,%5,%6,%7}, {%8,%9}, {%0,%1,%2,%3};"
        : "+f"(c[0]), "+f"(c[1]), "+f"(c[2]), "+f"(c[3])
        : "r"(a[0]), "r"(a[1]), "r"(a[2]), "r"(a[3]), "r"(b[0]), "r"(b[1]));
}

// ===========================================================================
// Merged prep: blocks [0,4096) transpose+round the 4 weight matrices;
// blocks [4096,12288) do RoPE + x rounding + counter reset.
// ===========================================================================
__global__ void prep_all(const float* __restrict__ x,
                         const float* __restrict__ w0, const float* __restrict__ w1,
                         const float* __restrict__ w2, const float* __restrict__ w3) {
    if (blockIdx.x < 4096) {
        __shared__ float t[32][33];
        const int z   = blockIdx.x >> 10;
        const int rem = blockIdx.x & 1023;
        const int n0  = (rem & 31) * 32;
        const int k0  = (rem >> 5) * 32;
        const int tx  = threadIdx.x & 31;
        const int ty  = threadIdx.x >> 5;     // 0..7
        const float* w = (z == 0) ? w0 : (z == 1) ? w1 : (z == 2) ? w2 : w3;
        for (int r = ty; r < 32; r += 8)
            t[r][tx] = w[(size_t)(k0 + r) * DIM + n0 + tx];
        __syncthreads();
        __half* o = g_wr + (size_t)z * DIM * DIM;
        for (int r = ty; r < 32; r += 8)
            o[(size_t)(n0 + r) * DIM + k0 + tx] = __float2half_rn(t[tx][r]);
    } else {
        int idx = (blockIdx.x - 4096) * 256 + threadIdx.x;   // NTOK*512
        if (idx == 0) g_tctr = 0;
        int t   = idx >> 9;
        int rem = idx & 511;
        int h   = rem >> 5;
        int i   = rem & 31;
        int s   = t & (SEQ - 1);

        float inv = expf(-(float)i * (9.210340371976184f / 32.0f));
        float ang = (float)s * inv;
        float sn, cs;
        sincosf(ang, &sn, &cs);

        const float* xp = x     + (size_t)t * DIM + h * HDIM;
        __half*      qp = g_qin + (size_t)t * DIM + h * HDIM;
        __half*      xr = g_xr  + (size_t)t * DIM + h * HDIM;
        float x1 = xp[i];
        float x2 = xp[i + 32];
        qp[i]      = __float2half_rn(x1 * cs - x2 * sn);
        qp[i + 32] = __float2half_rn(x2 * cs + x1 * sn);
        xr[i]      = __float2half_rn(x1);
        xr[i + 32] = __float2half_rn(x2);
    }
}

// ===========================================================================
// FP16 GEMM (unchanged): CTA 128x128, 256 thr, warp tile 32x64, BK=64,
// 3-stage cp.async, ldmatrix; 110.6KB smem -> 2 CTAs/SM.
// ===========================================================================
#define RSTRH 72
#define A_BYTES (128 * RSTRH * 2)      // 18432
#define B_BYTES (128 * RSTRH * 2)      // 18432
#define SSZ     (A_BYTES + B_BYTES)    // 36864
#define GEMM_SMEM_BYTES (3 * SSZ)      // 110592
#define NCHUNK  (DIM / 64)             // 16

extern __shared__ uint32_t dsm[];

template <int MODE, typename OutT>
__device__ __forceinline__ void gemm_body(const __half* __restrict__ A,
                                          const __half* __restrict__ Wt,
                                          OutT* __restrict__ C,
                                          int row0, int col0) {
    const int tid  = threadIdx.x;
    const int wid  = tid >> 5;
    const int lane = tid & 31;
    const int gid  = lane >> 2;
    const int tig  = lane & 3;
    const int wm   = wid >> 1;
    const int wn   = wid & 1;
    const int mi   = lane >> 3;
    const int lr   = lane & 7;

    const uint32_t sb = smem_u32(dsm);

    const uint32_t a_lane = ((wm * 32 + (mi & 1) * 8 + lr) * RSTRH + (mi >> 1) * 8) * 2;
    const uint32_t b_lane = ((wn * 64 + (mi >> 1) * 8 + lr) * RSTRH + (mi & 1) * 8) * 2;

    float acc[2][8][4];
#pragma unroll
    for (int i = 0; i < 2; i++)
#pragma unroll
        for (int j = 0; j < 8; j++)
#pragma unroll
            for (int r = 0; r < 4; r++) acc[i][j][r] = 0.0f;

#define ISSUE_STAGE(s, c)                                                        \
    {                                                                            \
        uint32_t ab = sb + (s) * SSZ;                                            \
        uint32_t bb = ab + A_BYTES;                                              \
        _Pragma("unroll")                                                        \
        for (int it = 0; it < 4; it++) {                                         \
            int idx = it * 256 + tid;                                            \
            int m = idx >> 3, k8 = idx & 7;                                      \
            CPA(ab + m * 144 + k8 * 16,                                          \
                A + (size_t)(row0 + m) * DIM + (c) * 64 + k8 * 8);               \
            CPA(bb + m * 144 + k8 * 16,                                          \
                Wt + (size_t)(col0 + m) * DIM + (c) * 64 + k8 * 8);              \
        }                                                                        \
        CPC();                                                                   \
    }

    ISSUE_STAGE(0, 0);
    ISSUE_STAGE(1, 1);

    int s = 0;
    for (int c = 0; c < NCHUNK; c++) {
        CPW(1);
        __syncthreads();
        if (c + 2 < NCHUNK) {
            int sn = (s + 2 >= 3) ? s - 1 : s + 2;
            ISSUE_STAGE(sn, c + 2);
        }

        const uint32_t abase = sb + s * SSZ;
        const uint32_t bbase = abase + A_BYTES;
#pragma unroll
        for (int ss = 0; ss < 4; ss++) {
            const int ksf = ss * 32;
            uint32_t af[2][4], bf[8][2];
#pragma unroll
            for (int i = 0; i < 2; i++)
                LDM4(af[i][0], af[i][1], af[i][2], af[i][3],
                     abase + a_lane + i * (16 * RSTRH * 2) + ksf);
#pragma unroll
            for (int jj = 0; jj < 4; jj++)
                LDM4(bf[2 * jj][0], bf[2 * jj][1], bf[2 * jj + 1][0], bf[2 * jj + 1][1],
                     bbase + b_lane + jj * (16 * RSTRH * 2) + ksf);
#pragma unroll
            for (int i = 0; i < 2; i++)
#pragma unroll
                for (int j = 0; j < 8; j++)
                    mma_f16(acc[i][j], af[i], bf[j]);
        }
        s = (s + 1 == 3) ? 0 : s + 1;
    }

#pragma unroll
    for (int i = 0; i < 2; i++) {
        int r0 = row0 + wm * 32 + i * 16 + gid;
#pragma unroll
        for (int j = 0; j < 8; j++) {
            int cc = col0 + wn * 64 + j * 8 + tig * 2;
            if (MODE == 0) {
                float* Cf = (float*)C;
                *(float2*)(Cf + (size_t)r0 * DIM + cc)       = make_float2(acc[i][j][0], acc[i][j][1]);
                *(float2*)(Cf + (size_t)(r0 + 8) * DIM + cc) = make_float2(acc[i][j][2], acc[i][j][3]);
            } else if (MODE == 1) {
                __half* Ch = (__half*)C;
                *(__half2*)(Ch + (size_t)r0 * DIM + cc) =
                    __floats2half2_rn(acc[i][j][0], acc[i][j][1]);
                *(__half2*)(Ch + (size_t)(r0 + 8) * DIM + cc) =
                    __floats2half2_rn(acc[i][j][2], acc[i][j][3]);
            } else {
                __half* Ch = (__half*)C;
                int b0 = r0 >> 11, s0 = r0 & 2047;
                int hh = cc >> 6,  dd = cc & 63;
                __half* base = Ch + ((size_t)(b0 * HEADS + hh) * HDIM) * SEQ;
                base[(size_t)(dd)     * SEQ + s0] = __float2half_rn(acc[i][j][0]);
                base[(size_t)(dd + 1) * SEQ + s0] = __float2half_rn(acc[i][j][1]);
                int r1 = r0 + 8;
                int b1 = r1 >> 11, s1 = r1 & 2047;
                __half* base1 = Ch + ((size_t)(b1 * HEADS + hh) * HDIM) * SEQ;
                base1[(size_t)(dd)     * SEQ + s1] = __float2half_rn(acc[i][j][2]);
                base1[(size_t)(dd + 1) * SEQ + s1] = __float2half_rn(acc[i][j][3]);
            }
        }
    }
}

#define QKV_TILES 768

__global__ __launch_bounds__(256, 2)
void gemm_qkv() {
    __shared__ unsigned int s_tile;
    for (;;) {
        __syncthreads();
        if (threadIdx.x == 0) s_tile = atomicAdd(&g_tctr, 1u);
        __syncthreads();
        unsigned int tile = s_tile;
        if (tile >= QKV_TILES) return;

        const int mi   = tile >> 8;
        const int rem  = tile & 255;
        const int row0 = (rem >> 3) * 128;
        const int col0 = (rem & 7) * 128;
        const __half* Wt = g_wr + (size_t)mi * DIM * DIM;
        if (mi == 0)      gemm_body<1>(g_qin, Wt, g_q,  row0, col0);
        else if (mi == 1) gemm_body<1>(g_qin, Wt, g_k,  row0, col0);
        else              gemm_body<2>(g_xr,  Wt, g_vt, row0, col0);
    }
}

__global__ __launch_bounds__(256, 2)
void gemm_out(float* __restrict__ out) {
    gemm_body<0>(g_ao, g_wr + (size_t)3 * DIM * DIM, out, blockIdx.y * 128, blockIdx.x * 128);
}

// ===========================================================================
// FP16 MMA attention v4: P kept entirely in REGISTERS (S C-frag == P A-frag
// layout identity) — no P smem, no syncwarp, no P ldmatrix. Double-buffered
// K/V, warp-uniform mask specialization + per-k16-block P.V skipping.
// smem halves: Q[128*72] | K0|V0|K1|V1 [64*72 each]  = 55296 B
// ===========================================================================
#define KVSZ (64 * RSTRH * 2)          // 9216 B
#define ATTN_SMEM_BYTES (128*RSTRH*2 + 4*KVSZ)   // 55296

__global__ __launch_bounds__(256, 3)
void attn_mma() {
    extern __shared__ __half afh[];

    const int tid  = threadIdx.x;
    const int wid  = tid >> 5;
    const int lane = tid & 31;
    const int gid  = lane >> 2;
    const int tig  = lane & 3;
    const int mi   = lane >> 3;
    const int lr   = lane & 7;

    const int qt = blockIdx.x, h = blockIdx.y, b = blockIdx.z;
    const int q0 = qt * 128;

    const uint32_t sb = smem_u32(afh);
    const uint32_t Qb = sb;
    const uint32_t KV0 = sb + 128 * RSTRH * 2;

    const __half* Qg = g_q + ((size_t)(b * SEQ + q0)) * DIM + h * HDIM;
#pragma unroll
    for (int it = 0; it < 4; it++) {
        int idx = it * 256 + tid;
        int r = idx >> 3, c8 = idx & 7;
        CPA(Qb + r * 144 + c8 * 16, Qg + (size_t)r * DIM + c8 * 8);
    }
    CPC();

    const __half* Kgb = g_k  + ((size_t)(b * SEQ)) * DIM + h * HDIM;
    const __half* Vgb = g_vt + ((size_t)((b * HEADS + h) * HDIM)) * SEQ;

#define ISSUE_KV(kt0, nb)                                                        \
    {                                                                            \
        uint32_t kb = KV0 + (nb) * 2 * KVSZ;                                     \
        uint32_t vb = kb + KVSZ;                                                 \
        const __half* Kg = Kgb + (size_t)(kt0) * DIM;                            \
        const __half* Vg = Vgb + (kt0);                                          \
        _Pragma("unroll")                                                        \
        for (int it = 0; it < 2; it++) {                                         \
            int idx = it * 256 + tid;                                            \
            int r = idx >> 3, c8 = idx & 7;                                      \
            CPA(kb + r * 144 + c8 * 16, Kg + (size_t)r * DIM + c8 * 8);          \
            CPA(vb + r * 144 + c8 * 16, Vg + (size_t)r * SEQ + c8 * 8);          \
        }                                                                        \
        CPC();                                                                   \
    }

    const uint32_t a_q = Qb + ((16 * wid + (mi & 1) * 8 + lr) * RSTRH + (mi >> 1) * 8) * 2;
    const uint32_t boff = ((mi >> 1) * 8 + lr) * 144 + (mi & 1) * 16;

    float o[8][4];
#pragma unroll
    for (int j = 0; j < 8; j++)
#pragma unroll
        for (int r = 0; r < 4; r++) o[j][r] = 0.0f;
    float lp0 = 0.0f, lp1 = 0.0f;
    const int r0g = q0 + 16 * wid + gid;

    const int p_lo = (q0 == 0) ? 2 : 0;
    const int p_hi = min(5, (SEQ + 64 - q0) / 64);

    ISSUE_KV(q0 - 128 + p_lo * 64, 0);

    int nb = 0;
    for (int p = p_lo; p <= p_hi; p++) {
        const int kt0 = q0 - 128 + p * 64;

        __syncthreads();
        if (p < p_hi) { ISSUE_KV(kt0 + 64, nb ^ 1); CPW(1); }
        else CPW(0);
        __syncthreads();

        const int d = q0 + 16 * wid - kt0;     // warp-uniform
        if (d > -143 && d < 191) {
            const uint32_t kbuf = KV0 + nb * 2 * KVSZ;
            const uint32_t vbuf = kbuf + KVSZ;
            const bool full = (d >= -64) && (d <= 112);

            uint32_t ph01[8], ph23[8];         // P fragments (half2 packed)

            // ---- S = Q K^T in two j-halves; mask+exp into registers ----
#pragma unroll
            for (int jh = 0; jh < 2; jh++) {
                float sc[4][4];
#pragma unroll
                for (int j = 0; j < 4; j++)
#pragma unroll
                    for (int r = 0; r < 4; r++) sc[j][r] = 0.0f;
#pragma unroll
                for (int ss = 0; ss < 4; ss++) {
                    uint32_t aq[4], bf[4][2];
                    LDM4(aq[0], aq[1], aq[2], aq[3], a_q + ss * 32);
#pragma unroll
                    for (int jj = 0; jj < 2; jj++)
                        LDM4(bf[2*jj][0], bf[2*jj][1], bf[2*jj+1][0], bf[2*jj+1][1],
                             kbuf + (jh * 2 + jj) * (16 * RSTRH * 2) + boff + ss * 32);
#pragma unroll
                    for (int j = 0; j < 4; j++) mma_f16(sc[j], aq, bf[j]);
                }

#pragma unroll
                for (int j = 0; j < 4; j++) {
                    const int jg = jh * 4 + j;
                    if (full) {
                        float e0 = __expf(sc[j][0] * SCALE);
                        float e1 = __expf(sc[j][1] * SCALE);
                        float e2 = __expf(sc[j][2] * SCALE);
                        float e3 = __expf(sc[j][3] * SCALE);
                        lp0 += e0 + e1;
                        lp1 += e2 + e3;
                        ph01[jg] = pack_h2(e0, e1);
                        ph23[jg] = pack_h2(e2, e3);
                    } else {
                        const int dj = d - 8 * jg;
                        if (dj >= 135 || dj <= -143) {
                            ph01[jg] = 0u;
                            ph23[jg] = 0u;
                        } else {
                            int col = kt0 + jg * 8 + 2 * tig;
                            float e0 = (abs(r0g - col)     < WIN) ? __expf(sc[j][0] * SCALE) : 0.0f;
                            float e1 = (abs(r0g - col - 1) < WIN) ? __expf(sc[j][1] * SCALE) : 0.0f;
                            float e2 = (abs(r0g + 8 - col)     < WIN) ? __expf(sc[j][2] * SCALE) : 0.0f;
                            float e3 = (abs(r0g + 8 - col - 1) < WIN) ? __expf(sc[j][3] * SCALE) : 0.0f;
                            lp0 += e0 + e1;
                            lp1 += e2 + e3;
                            ph01[jg] = pack_h2(e0, e1);
                            ph23[jg] = pack_h2(e2, e3);
                        }
                    }
                }
            }

            // ---- O += P V  (P straight from registers; skip dead k16 blocks) ----
#pragma unroll
            for (int ss = 0; ss < 4; ss++) {
                if (!full) {
                    const int d0 = d - 8 * (2 * ss);
                    const int d1 = d - 8 * (2 * ss + 1);
                    if ((d0 >= 135 || d0 <= -143) && (d1 >= 135 || d1 <= -143))
                        continue;                      // warp-uniform skip
                }
                uint32_t ap[4] = {ph01[2*ss], ph23[2*ss], ph01[2*ss+1], ph23[2*ss+1]};
                uint32_t bf[8][2];
#pragma unroll
                for (int jj = 0; jj < 4; jj++)
                    LDM4(bf[2*jj][0], bf[2*jj][1], bf[2*jj+1][0], bf[2*jj+1][1],
                         vbuf + jj * (16 * RSTRH * 2) + boff + ss * 32);
#pragma unroll
                for (int j = 0; j < 8; j++) mma_f16(o[j], ap, bf[j]);
            }
        }
        nb ^= 1;
    }

    lp0 += __shfl_xor_sync(0xffffffff, lp0, 1);
    lp0 += __shfl_xor_sync(0xffffffff, lp0, 2);
    lp1 += __shfl_xor_sync(0xffffffff, lp1, 1);
    lp1 += __shfl_xor_sync(0xffffffff, lp1, 2);
    const float inv0 = 1.0f / lp0;
    const float inv1 = 1.0f / lp1;

    __half* Og = g_ao + ((size_t)(b * SEQ + r0g)) * DIM + h * HDIM;
#pragma unroll
    for (int j = 0; j < 8; j++) {
        int c = j * 8 + 2 * tig;
        *(__half2*)(Og + c) = __floats2half2_rn(o[j][0] * inv0, o[j][1] * inv0);
        *(__half2*)(Og + (size_t)8 * DIM + c) = __floats2half2_rn(o[j][2] * inv1, o[j][3] * inv1);
    }
}

// ===========================================================================
extern "C" void kernel_launch(void* const* d_in, const int* in_sizes, int n_in,
                              void* d_out, int out_size) {
    const float* x  = (const float*)d_in[0];
    const float* Wq = (const float*)d_in[1];
    const float* Wk = (const float*)d_in[2];
    const float* Wv = (const float*)d_in[3];
    const float* Wo = (const float*)d_in[4];
    float* out = (float*)d_out;

    cudaFuncSetAttribute(gemm_qkv,
                         cudaFuncAttributeMaxDynamicSharedMemorySize, GEMM_SMEM_BYTES);
    cudaFuncSetAttribute(gemm_out,
                         cudaFuncAttributeMaxDynamicSharedMemorySize, GEMM_SMEM_BYTES);
    cudaFuncSetAttribute(attn_mma,
                         cudaFuncAttributeMaxDynamicSharedMemorySize, ATTN_SMEM_BYTES);

    // 0+1. Weight prep + RoPE + x rounding (one launch; resets tile counter)
    prep_all<<<12288, 256>>>(x, Wq, Wk, Wv, Wo);

    // 2. Q,K,V projections — persistent, 296 CTAs (2/SM)
    gemm_qkv<<<296, 256, GEMM_SMEM_BYTES>>>();

    // 3. FP16 MMA windowed attention (register-P, 3 CTAs/SM)
    attn_mma<<<dim3(SEQ / 128, HEADS, BATCH), 256, ATTN_SMEM_BYTES>>>();

    // 4. Output projection -> d_out (fp32)
    gemm_out<<<dim3(8, 32), 256, GEMM_SMEM_BYTES>>>(out);
    (void)in_sizes; (void)n_in; (void)out_size;
}

// round 16
// speedup vs baseline: 1.0145x; 1.0046x over previous
#include <cuda_runtime.h>
#include <cuda_fp16.h>
#include <math.h>
#include <cstdint>

#define BATCH 2
#define SEQ   2048
#define NTOK  (BATCH*SEQ)      // 4096
#define DIM   1024
#define HEADS 16
#define HDIM  64
#define WIN   128
#define SCALE 0.125f           // 1/sqrt(64)

// Scratch (device globals; no allocation allowed)
__device__ __half g_qin[NTOK*DIM];    // rope output, fp16
__device__ __half g_xr [NTOK*DIM];    // x, fp16
__device__ __half g_q  [NTOK*DIM];    // Q fp16
__device__ __half g_k  [NTOK*DIM];    // K fp16
__device__ __half g_vt [NTOK*DIM];    // V^T fp16: [(b*16+h)*64+d][s]
__device__ __half g_ao [NTOK*DIM];    // attention out fp16
__device__ __half g_wr [4*DIM*DIM];   // W^T fp16: [mat][n][k]
__device__ unsigned int g_tctr;       // persistent-GEMM tile counter

#define CPA(dst, src) \
    asm volatile("cp.async.cg.shared.global [%0], [%1], 16;" :: "r"(dst), "l"(src) : "memory")
#define CPC() asm volatile("cp.async.commit_group;" ::: "memory")
#define CPW(n) asm volatile("cp.async.wait_group %0;" :: "n"(n) : "memory")
#define LDM4(r0, r1, r2, r3, a) \
    asm volatile("ldmatrix.sync.aligned.m8n8.x4.shared.b16 {%0,%1,%2,%3}, [%4];" \
        : "=r"(r0), "=r"(r1), "=r"(r2), "=r"(r3) : "r"(a))

__device__ __forceinline__ uint32_t smem_u32(const void* p) {
    uint32_t a;
    asm("{ .reg .u64 t; cvta.to.shared.u64 t, %1; cvt.u32.u64 %0, t; }" : "=r"(a) : "l"(p));
    return a;
}

__device__ __forceinline__ uint32_t pack_h2(float a, float b) {
    __half2 t = __floats2half2_rn(a, b);
    return *(uint32_t*)&t;
}

__device__ __forceinline__ void mma_f16(float* c, const uint32_t* a, const uint32_t* b) {
    asm volatile(
        "mma.sync.aligned.m16n8k16.row.col.f32.f16.f16.f32 "
        "{%0,%1,%2,%3}, {%4,%5,%6,%7}, {%8,%9}, {%0,%1,%2,%3};"
        : "+f"(c[0]), "+f"(c[1]), "+f"(c[2]), "+f"(c[3])
        : "r"(a[0]), "r"(a[1]), "r"(a[2]), "r"(a[3]), "r"(b[0]), "r"(b[1]));
}

// ===========================================================================
// Merged prep:
//   blocks [0,4096): transpose + fp16-round the 4 weight matrices
//   blocks [4096,8192): RoPE + x rounding, ONE BLOCK PER TOKEN —
//     32 lanes compute the 32 sincos pairs once into smem (h-independent!),
//     then 256 threads apply them across all 16 heads. sincosf count drops
//     16x vs the per-(t,h,i) version; values are bit-identical.
// ===========================================================================
__global__ void prep_all(const float* __restrict__ x,
                         const float* __restrict__ w0, const float* __restrict__ w1,
                         const float* __restrict__ w2, const float* __restrict__ w3) {
    if (blockIdx.x < 4096) {
        __shared__ float t[32][33];
        const int z   = blockIdx.x >> 10;
        const int rem = blockIdx.x & 1023;
        const int n0  = (rem & 31) * 32;
        const int k0  = (rem >> 5) * 32;
        const int tx  = threadIdx.x & 31;
        const int ty  = threadIdx.x >> 5;     // 0..7
        const float* w = (z == 0) ? w0 : (z == 1) ? w1 : (z == 2) ? w2 : w3;
        for (int r = ty; r < 32; r += 8)
            t[r][tx] = w[(size_t)(k0 + r) * DIM + n0 + tx];
        __syncthreads();
        __half* o = g_wr + (size_t)z * DIM * DIM;
        for (int r = ty; r < 32; r += 8)
            o[(size_t)(n0 + r) * DIM + k0 + tx] = __float2half_rn(t[tx][r]);
    } else {
        __shared__ float cs[32], sn[32];
        const int t   = blockIdx.x - 4096;         // token 0..4095
        const int tid = threadIdx.x;
        if (t == 0 && tid == 0) g_tctr = 0;

        if (tid < 32) {
            const int s = t & (SEQ - 1);
            float inv = expf(-(float)tid * (9.210340371976184f / 32.0f));
            float ang = (float)s * inv;
            float s_, c_;
            sincosf(ang, &s_, &c_);
            sn[tid] = s_;
            cs[tid] = c_;
        }
        __syncthreads();

        const float* xp = x     + (size_t)t * DIM;
        __half*      qp = g_qin + (size_t)t * DIM;
        __half*      xr = g_xr  + (size_t)t * DIM;
#pragma unroll
        for (int k = 0; k < 2; k++) {
            int idx = k * 256 + tid;               // 0..511 = (h,i) pairs
            int h = idx >> 5;
            int i = idx & 31;
            float c_ = cs[i], s_ = sn[i];
            float x1 = xp[h * HDIM + i];
            float x2 = xp[h * HDIM + i + 32];
            qp[h * HDIM + i]      = __float2half_rn(x1 * c_ - x2 * s_);
            qp[h * HDIM + i + 32] = __float2half_rn(x2 * c_ + x1 * s_);
            xr[h * HDIM + i]      = __float2half_rn(x1);
            xr[h * HDIM + i + 32] = __float2half_rn(x2);
        }
    }
}

// ===========================================================================
// FP16 GEMM (unchanged): CTA 128x128, 256 thr, warp tile 32x64, BK=64,
// 3-stage cp.async, ldmatrix; 110.6KB smem -> 2 CTAs/SM.
// ===========================================================================
#define RSTRH 72
#define A_BYTES (128 * RSTRH * 2)      // 18432
#define B_BYTES (128 * RSTRH * 2)      // 18432
#define SSZ     (A_BYTES + B_BYTES)    // 36864
#define GEMM_SMEM_BYTES (3 * SSZ)      // 110592
#define NCHUNK  (DIM / 64)             // 16

extern __shared__ uint32_t dsm[];

template <int MODE, typename OutT>
__device__ __forceinline__ void gemm_body(const __half* __restrict__ A,
                                          const __half* __restrict__ Wt,
                                          OutT* __restrict__ C,
                                          int row0, int col0) {
    const int tid  = threadIdx.x;
    const int wid  = tid >> 5;
    const int lane = tid & 31;
    const int gid  = lane >> 2;
    const int tig  = lane & 3;
    const int wm   = wid >> 1;
    const int wn   = wid & 1;
    const int mi   = lane >> 3;
    const int lr   = lane & 7;

    const uint32_t sb = smem_u32(dsm);

    const uint32_t a_lane = ((wm * 32 + (mi & 1) * 8 + lr) * RSTRH + (mi >> 1) * 8) * 2;
    const uint32_t b_lane = ((wn * 64 + (mi >> 1) * 8 + lr) * RSTRH + (mi & 1) * 8) * 2;

    float acc[2][8][4];
#pragma unroll
    for (int i = 0; i < 2; i++)
#pragma unroll
        for (int j = 0; j < 8; j++)
#pragma unroll
            for (int r = 0; r < 4; r++) acc[i][j][r] = 0.0f;

#define ISSUE_STAGE(s, c)                                                        \
    {                                                                            \
        uint32_t ab = sb + (s) * SSZ;                                            \
        uint32_t bb = ab + A_BYTES;                                              \
        _Pragma("unroll")                                                        \
        for (int it = 0; it < 4; it++) {                                         \
            int idx = it * 256 + tid;                                            \
            int m = idx >> 3, k8 = idx & 7;                                      \
            CPA(ab + m * 144 + k8 * 16,                                          \
                A + (size_t)(row0 + m) * DIM + (c) * 64 + k8 * 8);               \
            CPA(bb + m * 144 + k8 * 16,                                          \
                Wt + (size_t)(col0 + m) * DIM + (c) * 64 + k8 * 8);              \
        }                                                                        \
        CPC();                                                                   \
    }

    ISSUE_STAGE(0, 0);
    ISSUE_STAGE(1, 1);

    int s = 0;
    for (int c = 0; c < NCHUNK; c++) {
        CPW(1);
        __syncthreads();
        if (c + 2 < NCHUNK) {
            int sn2 = (s + 2 >= 3) ? s - 1 : s + 2;
            ISSUE_STAGE(sn2, c + 2);
        }

        const uint32_t abase = sb + s * SSZ;
        const uint32_t bbase = abase + A_BYTES;
#pragma unroll
        for (int ss = 0; ss < 4; ss++) {
            const int ksf = ss * 32;
            uint32_t af[2][4], bf[8][2];
#pragma unroll
            for (int i = 0; i < 2; i++)
                LDM4(af[i][0], af[i][1], af[i][2], af[i][3],
                     abase + a_lane + i * (16 * RSTRH * 2) + ksf);
#pragma unroll
            for (int jj = 0; jj < 4; jj++)
                LDM4(bf[2 * jj][0], bf[2 * jj][1], bf[2 * jj + 1][0], bf[2 * jj + 1][1],
                     bbase + b_lane + jj * (16 * RSTRH * 2) + ksf);
#pragma unroll
            for (int i = 0; i < 2; i++)
#pragma unroll
                for (int j = 0; j < 8; j++)
                    mma_f16(acc[i][j], af[i], bf[j]);
        }
        s = (s + 1 == 3) ? 0 : s + 1;
    }

#pragma unroll
    for (int i = 0; i < 2; i++) {
        int r0 = row0 + wm * 32 + i * 16 + gid;
#pragma unroll
        for (int j = 0; j < 8; j++) {
            int cc = col0 + wn * 64 + j * 8 + tig * 2;
            if (MODE == 0) {
                float* Cf = (float*)C;
                *(float2*)(Cf + (size_t)r0 * DIM + cc)       = make_float2(acc[i][j][0], acc[i][j][1]);
                *(float2*)(Cf + (size_t)(r0 + 8) * DIM + cc) = make_float2(acc[i][j][2], acc[i][j][3]);
            } else if (MODE == 1) {
                __half* Ch = (__half*)C;
                *(__half2*)(Ch + (size_t)r0 * DIM + cc) =
                    __floats2half2_rn(acc[i][j][0], acc[i][j][1]);
                *(__half2*)(Ch + (size_t)(r0 + 8) * DIM + cc) =
                    __floats2half2_rn(acc[i][j][2], acc[i][j][3]);
            } else {
                __half* Ch = (__half*)C;
                int b0 = r0 >> 11, s0 = r0 & 2047;
                int hh = cc >> 6,  dd = cc & 63;
                __half* base = Ch + ((size_t)(b0 * HEADS + hh) * HDIM) * SEQ;
                base[(size_t)(dd)     * SEQ + s0] = __float2half_rn(acc[i][j][0]);
                base[(size_t)(dd + 1) * SEQ + s0] = __float2half_rn(acc[i][j][1]);
                int r1 = r0 + 8;
                int b1 = r1 >> 11, s1 = r1 & 2047;
                __half* base1 = Ch + ((size_t)(b1 * HEADS + hh) * HDIM) * SEQ;
                base1[(size_t)(dd)     * SEQ + s1] = __float2half_rn(acc[i][j][2]);
                base1[(size_t)(dd + 1) * SEQ + s1] = __float2half_rn(acc[i][j][3]);
            }
        }
    }
}

#define QKV_TILES 768

__global__ __launch_bounds__(256, 2)
void gemm_qkv() {
    __shared__ unsigned int s_tile;
    for (;;) {
        __syncthreads();
        if (threadIdx.x == 0) s_tile = atomicAdd(&g_tctr, 1u);
        __syncthreads();
        unsigned int tile = s_tile;
        if (tile >= QKV_TILES) return;

        const int mi   = tile >> 8;
        const int rem  = tile & 255;
        const int row0 = (rem >> 3) * 128;
        const int col0 = (rem & 7) * 128;
        const __half* Wt = g_wr + (size_t)mi * DIM * DIM;
        if (mi == 0)      gemm_body<1>(g_qin, Wt, g_q,  row0, col0);
        else if (mi == 1) gemm_body<1>(g_qin, Wt, g_k,  row0, col0);
        else              gemm_body<2>(g_xr,  Wt, g_vt, row0, col0);
    }
}

__global__ __launch_bounds__(256, 2)
void gemm_out(float* __restrict__ out) {
    gemm_body<0>(g_ao, g_wr + (size_t)3 * DIM * DIM, out, blockIdx.y * 128, blockIdx.x * 128);
}

// ===========================================================================
// FP16 MMA attention v4 (unchanged): register-P, double-buffered K/V,
// warp-uniform mask specialization + per-k16-block P.V skipping; 3 CTAs/SM.
// smem halves: Q[128*72] | K0|V0|K1|V1 [64*72 each]  = 55296 B
// ===========================================================================
#define KVSZ (64 * RSTRH * 2)          // 9216 B
#define ATTN_SMEM_BYTES (128*RSTRH*2 + 4*KVSZ)   // 55296

__global__ __launch_bounds__(256, 3)
void attn_mma() {
    extern __shared__ __half afh[];

    const int tid  = threadIdx.x;
    const int wid  = tid >> 5;
    const int lane = tid & 31;
    const int gid  = lane >> 2;
    const int tig  = lane & 3;
    const int mi   = lane >> 3;
    const int lr   = lane & 7;

    const int qt = blockIdx.x, h = blockIdx.y, b = blockIdx.z;
    const int q0 = qt * 128;

    const uint32_t sb = smem_u32(afh);
    const uint32_t Qb = sb;
    const uint32_t KV0 = sb + 128 * RSTRH * 2;

    const __half* Qg = g_q + ((size_t)(b * SEQ + q0)) * DIM + h * HDIM;
#pragma unroll
    for (int it = 0; it < 4; it++) {
        int idx = it * 256 + tid;
        int r = idx >> 3, c8 = idx & 7;
        CPA(Qb + r * 144 + c8 * 16, Qg + (size_t)r * DIM + c8 * 8);
    }
    CPC();

    const __half* Kgb = g_k  + ((size_t)(b * SEQ)) * DIM + h * HDIM;
    const __half* Vgb = g_vt + ((size_t)((b * HEADS + h) * HDIM)) * SEQ;

#define ISSUE_KV(kt0, nb)                                                        \
    {                                                                            \
        uint32_t kb = KV0 + (nb) * 2 * KVSZ;                                     \
        uint32_t vb = kb + KVSZ;                                                 \
        const __half* Kg = Kgb + (size_t)(kt0) * DIM;                            \
        const __half* Vg = Vgb + (kt0);                                          \
        _Pragma("unroll")                                                        \
        for (int it = 0; it < 2; it++) {                                         \
            int idx = it * 256 + tid;                                            \
            int r = idx >> 3, c8 = idx & 7;                                      \
            CPA(kb + r * 144 + c8 * 16, Kg + (size_t)r * DIM + c8 * 8);          \
            CPA(vb + r * 144 + c8 * 16, Vg + (size_t)r * SEQ + c8 * 8);          \
        }                                                                        \
        CPC();                                                                   \
    }

    const uint32_t a_q = Qb + ((16 * wid + (mi & 1) * 8 + lr) * RSTRH + (mi >> 1) * 8) * 2;
    const uint32_t boff = ((mi >> 1) * 8 + lr) * 144 + (mi & 1) * 16;

    float o[8][4];
#pragma unroll
    for (int j = 0; j < 8; j++)
#pragma unroll
        for (int r = 0; r < 4; r++) o[j][r] = 0.0f;
    float lp0 = 0.0f, lp1 = 0.0f;
    const int r0g = q0 + 16 * wid + gid;

    const int p_lo = (q0 == 0) ? 2 : 0;
    const int p_hi = min(5, (SEQ + 64 - q0) / 64);

    ISSUE_KV(q0 - 128 + p_lo * 64, 0);

    int nb = 0;
    for (int p = p_lo; p <= p_hi; p++) {
        const int kt0 = q0 - 128 + p * 64;

        __syncthreads();
        if (p < p_hi) { ISSUE_KV(kt0 + 64, nb ^ 1); CPW(1); }
        else CPW(0);
        __syncthreads();

        const int d = q0 + 16 * wid - kt0;     // warp-uniform
        if (d > -143 && d < 191) {
            const uint32_t kbuf = KV0 + nb * 2 * KVSZ;
            const uint32_t vbuf = kbuf + KVSZ;
            const bool full = (d >= -64) && (d <= 112);

            uint32_t ph01[8], ph23[8];

#pragma unroll
            for (int jh = 0; jh < 2; jh++) {
                float sc[4][4];
#pragma unroll
                for (int j = 0; j < 4; j++)
#pragma unroll
                    for (int r = 0; r < 4; r++) sc[j][r] = 0.0f;
#pragma unroll
                for (int ss = 0; ss < 4; ss++) {
                    uint32_t aq[4], bf[4][2];
                    LDM4(aq[0], aq[1], aq[2], aq[3], a_q + ss * 32);
#pragma unroll
                    for (int jj = 0; jj < 2; jj++)
                        LDM4(bf[2*jj][0], bf[2*jj][1], bf[2*jj+1][0], bf[2*jj+1][1],
                             kbuf + (jh * 2 + jj) * (16 * RSTRH * 2) + boff + ss * 32);
#pragma unroll
                    for (int j = 0; j < 4; j++) mma_f16(sc[j], aq, bf[j]);
                }

#pragma unroll
                for (int j = 0; j < 4; j++) {
                    const int jg = jh * 4 + j;
                    if (full) {
                        float e0 = __expf(sc[j][0] * SCALE);
                        float e1 = __expf(sc[j][1] * SCALE);
                        float e2 = __expf(sc[j][2] * SCALE);
                        float e3 = __expf(sc[j][3] * SCALE);
                        lp0 += e0 + e1;
                        lp1 += e2 + e3;
                        ph01[jg] = pack_h2(e0, e1);
                        ph23[jg] = pack_h2(e2, e3);
                    } else {
                        const int dj = d - 8 * jg;
                        if (dj >= 135 || dj <= -143) {
                            ph01[jg] = 0u;
                            ph23[jg] = 0u;
                        } else {
                            int col = kt0 + jg * 8 + 2 * tig;
                            float e0 = (abs(r0g - col)     < WIN) ? __expf(sc[j][0] * SCALE) : 0.0f;
                            float e1 = (abs(r0g - col - 1) < WIN) ? __expf(sc[j][1] * SCALE) : 0.0f;
                            float e2 = (abs(r0g + 8 - col)     < WIN) ? __expf(sc[j][2] * SCALE) : 0.0f;
                            float e3 = (abs(r0g + 8 - col - 1) < WIN) ? __expf(sc[j][3] * SCALE) : 0.0f;
                            lp0 += e0 + e1;
                            lp1 += e2 + e3;
                            ph01[jg] = pack_h2(e0, e1);
                            ph23[jg] = pack_h2(e2, e3);
                        }
                    }
                }
            }

#pragma unroll
            for (int ss = 0; ss < 4; ss++) {
                if (!full) {
                    const int d0 = d - 8 * (2 * ss);
                    const int d1 = d - 8 * (2 * ss + 1);
                    if ((d0 >= 135 || d0 <= -143) && (d1 >= 135 || d1 <= -143))
                        continue;
                }
                uint32_t ap[4] = {ph01[2*ss], ph23[2*ss], ph01[2*ss+1], ph23[2*ss+1]};
                uint32_t bf[8][2];
#pragma unroll
                for (int jj = 0; jj < 4; jj++)
                    LDM4(bf[2*jj][0], bf[2*jj][1], bf[2*jj+1][0], bf[2*jj+1][1],
                         vbuf + jj * (16 * RSTRH * 2) + boff + ss * 32);
#pragma unroll
                for (int j = 0; j < 8; j++) mma_f16(o[j], ap, bf[j]);
            }
        }
        nb ^= 1;
    }

    lp0 += __shfl_xor_sync(0xffffffff, lp0, 1);
    lp0 += __shfl_xor_sync(0xffffffff, lp0, 2);
    lp1 += __shfl_xor_sync(0xffffffff, lp1, 1);
    lp1 += __shfl_xor_sync(0xffffffff, lp1, 2);
    const float inv0 = 1.0f / lp0;
    const float inv1 = 1.0f / lp1;

    __half* Og = g_ao + ((size_t)(b * SEQ + r0g)) * DIM + h * HDIM;
#pragma unroll
    for (int j = 0; j < 8; j++) {
        int c = j * 8 + 2 * tig;
        *(__half2*)(Og + c) = __floats2half2_rn(o[j][0] * inv0, o[j][1] * inv0);
        *(__half2*)(Og + (size_t)8 * DIM + c) = __floats2half2_rn(o[j][2] * inv1, o[j][3] * inv1);
    }
}

// ===========================================================================
extern "C" void kernel_launch(void* const* d_in, const int* in_sizes, int n_in,
                              void* d_out, int out_size) {
    const float* x  = (const float*)d_in[0];
    const float* Wq = (const float*)d_in[1];
    const float* Wk = (const float*)d_in[2];
    const float* Wv = (const float*)d_in[3];
    const float* Wo = (const float*)d_in[4];
    float* out = (float*)d_out;

    cudaFuncSetAttribute(gemm_qkv,
                         cudaFuncAttributeMaxDynamicSharedMemorySize, GEMM_SMEM_BYTES);
    cudaFuncSetAttribute(gemm_out,
                         cudaFuncAttributeMaxDynamicSharedMemorySize, GEMM_SMEM_BYTES);
    cudaFuncSetAttribute(attn_mma,
                         cudaFuncAttributeMaxDynamicSharedMemorySize, ATTN_SMEM_BYTES);

    // 0+1. Weight prep + RoPE (sincos deduplicated 16x) + x rounding
    prep_all<<<8192, 256>>>(x, Wq, Wk, Wv, Wo);

    // 2. Q,K,V projections — persistent, 296 CTAs (2/SM)
    gemm_qkv<<<296, 256, GEMM_SMEM_BYTES>>>();

    // 3. FP16 MMA windowed attention (register-P, 3 CTAs/SM)
    attn_mma<<<dim3(SEQ / 128, HEADS, BATCH), 256, ATTN_SMEM_BYTES>>>();

    // 4. Output projection -> d_out (fp32)
    gemm_out<<<dim3(8, 32), 256, GEMM_SMEM_BYTES>>>(out);
    (void)in_sizes; (void)n_in; (void)out_size;
}